// round 15
// baseline (speedup 1.0000x reference)
#include <cuda_runtime.h>
#include <math.h>

#define NN 50000
#define NE 800000
#define NH 4
#define NEG 0.2f

// ---------------- scratch (static device globals; no allocs allowed) ----------
__device__ float g_proj1[NN * 400];
__device__ float g_x1[NN * 400];
__device__ float g_proj2[NN * 512];
__device__ float g_el[NN * NH];
__device__ float g_er[NN * NH];
__device__ float g_wl1[300 * 8];
__device__ float g_wl2[400 * 8];
__device__ int   g_rowptr[NN + 1];
__device__ int   g_cnt[NN];
__device__ int   g_bsum[64];
__device__ int   g_ssrc[NE];

// ---------------- helpers ----------------------------------------------------
__device__ __forceinline__ float lrelu(float v) { return v > 0.f ? v : NEG * v; }

__device__ __forceinline__ unsigned f2tf32(float f) {
    unsigned r;
    asm("cvt.rna.tf32.f32 %0, %1;" : "=r"(r) : "f"(f));
    return r;
}

__device__ __forceinline__ void mma_tf32(float c[4], const unsigned a[4], const unsigned b[2]) {
    asm volatile(
        "mma.sync.aligned.m16n8k8.row.col.f32.tf32.tf32.f32 "
        "{%0,%1,%2,%3}, {%4,%5,%6,%7}, {%8,%9}, {%0,%1,%2,%3};"
        : "+f"(c[0]), "+f"(c[1]), "+f"(c[2]), "+f"(c[3])
        : "r"(a[0]), "r"(a[1]), "r"(a[2]), "r"(a[3]), "r"(b[0]), "r"(b[1]));
}

// ---------------- CSR build ---------------------------------------------------
__global__ void k_zero_int(int* p, int n) {
    int i = blockIdx.x * blockDim.x + threadIdx.x;
    if (i < n) p[i] = 0;
}

__global__ void k_hist(const int* __restrict__ dst, int* __restrict__ cnt) {
    int i = blockIdx.x * blockDim.x + threadIdx.x;
    if (i < NE) atomicAdd(&cnt[dst[i]], 1);
}

__global__ void k_scan1(const int* __restrict__ cnt, int* __restrict__ rowptr,
                        int* __restrict__ bsum) {
    __shared__ int sd[1024];
    int i = blockIdx.x * 1024 + threadIdx.x;
    int v = (i < NN) ? cnt[i] : 0;
    sd[threadIdx.x] = v;
    __syncthreads();
#pragma unroll
    for (int o = 1; o < 1024; o <<= 1) {
        int t = (threadIdx.x >= o) ? sd[threadIdx.x - o] : 0;
        __syncthreads();
        sd[threadIdx.x] += t;
        __syncthreads();
    }
    if (i < NN) rowptr[i + 1] = sd[threadIdx.x];
    if (threadIdx.x == 1023) bsum[blockIdx.x] = sd[1023];
}

__global__ void k_scan2(int* bsum, int nb) {
    if (threadIdx.x == 0) {
        int acc = 0;
        for (int b = 0; b < nb; b++) { int t = bsum[b]; bsum[b] = acc; acc += t; }
    }
}

__global__ void k_scan3(int* __restrict__ rowptr, const int* __restrict__ bsum,
                        int* __restrict__ cnt) {
    int i = blockIdx.x * blockDim.x + threadIdx.x;
    if (i < NN) {
        rowptr[i + 1] += bsum[i >> 10];
        cnt[i] = 0;
        if (i == 0) rowptr[0] = 0;
    }
}

__global__ void k_scatter(const int* __restrict__ src, const int* __restrict__ dst,
                          const int* __restrict__ rowptr, int* __restrict__ cnt,
                          int* __restrict__ ssrc) {
    int i = blockIdx.x * blockDim.x + threadIdx.x;
    if (i >= NE) return;
    int d = dst[i];
    int pos = rowptr[d] + atomicAdd(&cnt[d], 1);
    ssrc[pos] = src[i];
}

// ---------------- Wl precompute: Wlr[k][h8] = sum_d W[k, h*Dh+d] * av[h][d] --
__global__ void k_wl(const float* __restrict__ W, const float* __restrict__ al,
                     const float* __restrict__ ar, float* __restrict__ Wlr,
                     int K, int Dh) {
    int i = blockIdx.x * blockDim.x + threadIdx.x;
    if (i >= K * 8) return;
    int k = i >> 3, h8 = i & 7, h = h8 & 3;
    const float* av = (h8 < 4 ? al : ar) + h * Dh;
    const float* wrow = W + (size_t)k * (NH * Dh) + h * Dh;
    float s = 0.f;
    for (int d = 0; d < Dh; d++) s += wrow[d] * av[d];
    Wlr[k * 8 + h8] = s;
}

// ---------------- scores from layer input via Wl: warp per node --------------
// el[n][h] = sum_k x[n][k]*Wlr[k][h] ; er[n][h] = sum_k x[n][k]*Wlr[k][4+h]
__global__ void __launch_bounds__(128)
k_scores_wl(const float* __restrict__ x, const float* __restrict__ Wlr,
            float* __restrict__ el, float* __restrict__ er, int K) {
    int n = blockIdx.x * 4 + (threadIdx.x >> 5);
    if (n >= NN) return;
    int lane = threadIdx.x & 31;
    const float* xr = x + (size_t)n * K;
    float a0 = 0.f, a1 = 0.f, a2 = 0.f, a3 = 0.f;
    float b0 = 0.f, b1 = 0.f, b2 = 0.f, b3 = 0.f;
    for (int k = lane * 4; k < K; k += 128) {
        float4 xv = *(const float4*)(xr + k);
#pragma unroll
        for (int j = 0; j < 4; j++) {
            float xj = j == 0 ? xv.x : j == 1 ? xv.y : j == 2 ? xv.z : xv.w;
            const float4* w = (const float4*)(Wlr + (size_t)(k + j) * 8);
            float4 wl = w[0], wr = w[1];
            a0 += xj * wl.x; a1 += xj * wl.y; a2 += xj * wl.z; a3 += xj * wl.w;
            b0 += xj * wr.x; b1 += xj * wr.y; b2 += xj * wr.z; b3 += xj * wr.w;
        }
    }
#pragma unroll
    for (int o = 16; o; o >>= 1) {
        a0 += __shfl_xor_sync(0xffffffffu, a0, o);
        a1 += __shfl_xor_sync(0xffffffffu, a1, o);
        a2 += __shfl_xor_sync(0xffffffffu, a2, o);
        a3 += __shfl_xor_sync(0xffffffffu, a3, o);
        b0 += __shfl_xor_sync(0xffffffffu, b0, o);
        b1 += __shfl_xor_sync(0xffffffffu, b1, o);
        b2 += __shfl_xor_sync(0xffffffffu, b2, o);
        b3 += __shfl_xor_sync(0xffffffffu, b3, o);
    }
    if (lane == 0) {
        *(float4*)(el + n * 4) = make_float4(a0, a1, a2, a3);
        *(float4*)(er + n * 4) = make_float4(b0, b1, b2, b3);
    }
}

// ---------------- TF32 GEMM, register-staged double buffering (R10 proven) ---
#define BM 128
#define BN 128
#define BK 16
#define A_STRIDE (BK + 4)
#define B_STRIDE (BN + 8)

__device__ __forceinline__ void load_tileA(const float* __restrict__ A, int M, int K,
                                           int bm0, int k0, int tid, float4 pa[2]) {
#pragma unroll
    for (int u = 0; u < 2; u++) {
        int idx = tid + u * 256;
        int row = idx >> 2;
        int col = (idx & 3) * 4;
        int gm = bm0 + row, gk = k0 + col;
        float4 v = make_float4(0.f, 0.f, 0.f, 0.f);
        if (gm < M) {
            if (gk + 3 < K) v = *(const float4*)(A + (size_t)gm * K + gk);
            else {
                const float* ap = A + (size_t)gm * K;
                if (gk + 0 < K) v.x = ap[gk + 0];
                if (gk + 1 < K) v.y = ap[gk + 1];
                if (gk + 2 < K) v.z = ap[gk + 2];
            }
        }
        pa[u] = v;
    }
}

__device__ __forceinline__ void load_tileB(const float* __restrict__ B, int N, int K,
                                           int bn0, int k0, int tid, float4 pb[2]) {
#pragma unroll
    for (int u = 0; u < 2; u++) {
        int idx = tid + u * 256;
        int row = idx >> 5;
        int col = (idx & 31) * 4;
        int gk = k0 + row, gn = bn0 + col;
        float4 v = make_float4(0.f, 0.f, 0.f, 0.f);
        if (gk < K) {
            if (gn + 3 < N) v = *(const float4*)(B + (size_t)gk * N + gn);
            else {
                const float* bp = B + (size_t)gk * N;
                if (gn + 0 < N) v.x = bp[gn + 0];
                if (gn + 1 < N) v.y = bp[gn + 1];
                if (gn + 2 < N) v.z = bp[gn + 2];
            }
        }
        pb[u] = v;
    }
}

__device__ __forceinline__ void store_tileA(unsigned (*As)[A_STRIDE], int tid,
                                            const float4 pa[2]) {
#pragma unroll
    for (int u = 0; u < 2; u++) {
        int idx = tid + u * 256;
        int row = idx >> 2;
        int col = (idx & 3) * 4;
        As[row][col + 0] = f2tf32(pa[u].x);
        As[row][col + 1] = f2tf32(pa[u].y);
        As[row][col + 2] = f2tf32(pa[u].z);
        As[row][col + 3] = f2tf32(pa[u].w);
    }
}

__device__ __forceinline__ void store_tileB(unsigned (*Bs)[B_STRIDE], int tid,
                                            const float4 pb[2]) {
#pragma unroll
    for (int u = 0; u < 2; u++) {
        int idx = tid + u * 256;
        int row = idx >> 5;
        int col = (idx & 31) * 4;
        Bs[row][col + 0] = f2tf32(pb[u].x);
        Bs[row][col + 1] = f2tf32(pb[u].y);
        Bs[row][col + 2] = f2tf32(pb[u].z);
        Bs[row][col + 3] = f2tf32(pb[u].w);
    }
}

__global__ void __launch_bounds__(256, 2)
k_gemm_tf32(const float* __restrict__ A, const float* __restrict__ B,
            float* __restrict__ C, int M, int N, int K) {
    __shared__ unsigned As[2][BM][A_STRIDE];
    __shared__ unsigned Bs[2][BK][B_STRIDE];

    const int tid  = threadIdx.x;
    const int lane = tid & 31;
    const int warp = tid >> 5;
    const int g    = lane >> 2;
    const int t4   = lane & 3;
    const int wm   = warp & 1;
    const int wn   = warp >> 1;
    const int bm0  = blockIdx.y * BM;
    const int bn0  = blockIdx.x * BN;

    float c[4][4][4];
#pragma unroll
    for (int mi = 0; mi < 4; mi++)
#pragma unroll
        for (int ni = 0; ni < 4; ni++)
#pragma unroll
            for (int q = 0; q < 4; q++) c[mi][ni][q] = 0.f;

    const int nk = (K + BK - 1) / BK;
    float4 pa[2], pb[2];

    load_tileA(A, M, K, bm0, 0, tid, pa);
    load_tileB(B, N, K, bn0, 0, tid, pb);
    store_tileA(As[0], tid, pa);
    store_tileB(Bs[0], tid, pb);
    __syncthreads();

    int buf = 0;
    for (int kt = 0; kt < nk; kt++) {
        if (kt + 1 < nk) {
            load_tileA(A, M, K, bm0, (kt + 1) * BK, tid, pa);
            load_tileB(B, N, K, bn0, (kt + 1) * BK, tid, pb);
        }

#pragma unroll
        for (int kk = 0; kk < BK; kk += 8) {
            unsigned af[4][4], bf[4][2];
#pragma unroll
            for (int mi = 0; mi < 4; mi++) {
                int r0 = wm * 64 + mi * 16;
                af[mi][0] = As[buf][r0 + g    ][kk + t4    ];
                af[mi][1] = As[buf][r0 + g + 8][kk + t4    ];
                af[mi][2] = As[buf][r0 + g    ][kk + t4 + 4];
                af[mi][3] = As[buf][r0 + g + 8][kk + t4 + 4];
            }
#pragma unroll
            for (int ni = 0; ni < 4; ni++) {
                int c0 = wn * 32 + ni * 8;
                bf[ni][0] = Bs[buf][kk + t4    ][c0 + g];
                bf[ni][1] = Bs[buf][kk + t4 + 4][c0 + g];
            }
#pragma unroll
            for (int mi = 0; mi < 4; mi++)
#pragma unroll
                for (int ni = 0; ni < 4; ni++)
                    mma_tf32(c[mi][ni], af[mi], bf[ni]);
        }

        if (kt + 1 < nk) {
            store_tileA(As[buf ^ 1], tid, pa);
            store_tileB(Bs[buf ^ 1], tid, pb);
        }
        __syncthreads();
        buf ^= 1;
    }

#pragma unroll
    for (int mi = 0; mi < 4; mi++) {
        int row0 = bm0 + wm * 64 + mi * 16;
#pragma unroll
        for (int ni = 0; ni < 4; ni++) {
            int col0 = bn0 + wn * 32 + ni * 8 + 2 * t4;
            int r = row0 + g;
            if (r < M) {
                if (col0     < N) C[(size_t)r * N + col0    ] = c[mi][ni][0];
                if (col0 + 1 < N) C[(size_t)r * N + col0 + 1] = c[mi][ni][1];
            }
            r = row0 + g + 8;
            if (r < M) {
                if (col0     < N) C[(size_t)r * N + col0    ] = c[mi][ni][2];
                if (col0 + 1 < N) C[(size_t)r * N + col0 + 1] = c[mi][ni][3];
            }
        }
    }
}

// ---------------- fused per-dst-node softmax + aggregate + bias + act --------
template <int DH>
__global__ void __launch_bounds__(128)
k_node(const float* __restrict__ proj, const float* __restrict__ el,
       const float* __restrict__ er, const int* __restrict__ rowptr,
       const int* __restrict__ ssrc, const float* __restrict__ bias,
       float* __restrict__ out, int act) {
    const int F = NH * DH;
    int n = blockIdx.x;
    int tid = threadIdx.x, w = tid >> 5, lane = tid & 31;
    int beg = rowptr[n], deg = rowptr[n + 1] - beg;
    float* o = out + (size_t)n * F;

    if (deg == 0) {
        for (int f = tid; f < F; f += 128) {
            float v = bias[f];
            o[f] = act ? lrelu(v) : v;
        }
        return;
    }

    __shared__ float s_er[NH], s_m[NH], s_is[NH];
    __shared__ float s_alpha[32 * NH];
    __shared__ int   s_src[32];
    if (tid < NH) s_er[tid] = er[n * NH + tid];
    __syncthreads();

    float erw = s_er[w];
    float mx = -INFINITY;
    for (int e = lane; e < deg; e += 32) {
        int s = ssrc[beg + e];
        mx = fmaxf(mx, lrelu(el[s * NH + w] + erw));
    }
#pragma unroll
    for (int off = 16; off; off >>= 1) mx = fmaxf(mx, __shfl_xor_sync(0xffffffffu, mx, off));
    float sum = 0.f;
    for (int e = lane; e < deg; e += 32) {
        int s = ssrc[beg + e];
        sum += expf(lrelu(el[s * NH + w] + erw) - mx);
    }
#pragma unroll
    for (int off = 16; off; off >>= 1) sum += __shfl_xor_sync(0xffffffffu, sum, off);
    if (lane == 0) { s_m[w] = mx; s_is[w] = 1.f / (sum + 1e-9f); }

    const int f = tid * 4;
    const int h = f / DH;
    float4 acc = make_float4(0.f, 0.f, 0.f, 0.f);

    for (int c0 = 0; c0 < deg; c0 += 32) {
        int cn = min(32, deg - c0);
        __syncthreads();
        for (int i = tid; i < cn * NH; i += 128) {
            int e = i >> 2, hh = i & 3;
            int s = ssrc[beg + c0 + e];
            if (hh == 0) s_src[e] = s;
            s_alpha[i] = expf(lrelu(el[s * NH + hh] + s_er[hh]) - s_m[hh]) * s_is[hh];
        }
        __syncthreads();
        if (f < F) {
            if (cn == 32) {
#pragma unroll 4
                for (int e = 0; e < 32; e++) {
                    float a = s_alpha[e * NH + h];
                    float4 v = *(const float4*)(proj + (size_t)s_src[e] * F + f);
                    acc.x += v.x * a;
                    acc.y += v.y * a;
                    acc.z += v.z * a;
                    acc.w += v.w * a;
                }
            } else {
                for (int e = 0; e < cn; e++) {
                    float a = s_alpha[e * NH + h];
                    float4 v = *(const float4*)(proj + (size_t)s_src[e] * F + f);
                    acc.x += v.x * a;
                    acc.y += v.y * a;
                    acc.z += v.z * a;
                    acc.w += v.w * a;
                }
            }
        }
    }

    if (f < F) {
        float4 b4 = *(const float4*)(bias + f);
        float4 r;
        r.x = acc.x + b4.x; r.y = acc.y + b4.y;
        r.z = acc.z + b4.z; r.w = acc.w + b4.w;
        if (act) { r.x = lrelu(r.x); r.y = lrelu(r.y); r.z = lrelu(r.z); r.w = lrelu(r.w); }
        *(float4*)(o + f) = r;
    }
}

// ---------------- launch -----------------------------------------------------
extern "C" void kernel_launch(void* const* d_in, const int* in_sizes, int n_in,
                              void* d_out, int out_size) {
    const float* init_emb = (const float*)d_in[0];
    const float* W1  = (const float*)d_in[1];
    const float* al1 = (const float*)d_in[2];
    const float* ar1 = (const float*)d_in[3];
    const float* b1  = (const float*)d_in[4];
    const float* W2  = (const float*)d_in[5];
    const float* al2 = (const float*)d_in[6];
    const float* ar2 = (const float*)d_in[7];
    const float* b2  = (const float*)d_in[8];
    const int*   src = (const int*)d_in[9];
    const int*   dst = (const int*)d_in[10];
    float* out = (float*)d_out;

    float *proj1, *x1, *proj2, *el, *er, *wl1, *wl2;
    int *rowptr, *cnt, *bsum, *ssrc;
    cudaGetSymbolAddress((void**)&proj1,  g_proj1);
    cudaGetSymbolAddress((void**)&x1,     g_x1);
    cudaGetSymbolAddress((void**)&proj2,  g_proj2);
    cudaGetSymbolAddress((void**)&el,     g_el);
    cudaGetSymbolAddress((void**)&er,     g_er);
    cudaGetSymbolAddress((void**)&wl1,    g_wl1);
    cudaGetSymbolAddress((void**)&wl2,    g_wl2);
    cudaGetSymbolAddress((void**)&rowptr, g_rowptr);
    cudaGetSymbolAddress((void**)&cnt,    g_cnt);
    cudaGetSymbolAddress((void**)&bsum,   g_bsum);
    cudaGetSymbolAddress((void**)&ssrc,   g_ssrc);

    dim3 t256(256);
    const int nScanBlocks = (NN + 1023) / 1024;
    const int nScoreBlocks = (NN + 3) / 4;

    static cudaStream_t s_side = nullptr;
    static cudaEvent_t  s_evFork = nullptr, s_evS1 = nullptr, s_evJoin = nullptr,
                        s_evX1 = nullptr, s_evS2 = nullptr;
    if (!s_side) {
        if (cudaStreamCreateWithFlags(&s_side, cudaStreamNonBlocking) != cudaSuccess)
            s_side = nullptr;
        if (s_side) {
            cudaEventCreateWithFlags(&s_evFork, cudaEventDisableTiming);
            cudaEventCreateWithFlags(&s_evS1,   cudaEventDisableTiming);
            cudaEventCreateWithFlags(&s_evJoin, cudaEventDisableTiming);
            cudaEventCreateWithFlags(&s_evX1,   cudaEventDisableTiming);
            cudaEventCreateWithFlags(&s_evS2,   cudaEventDisableTiming);
        }
    }

    cudaStream_t main_s = 0;
    cudaStream_t side_s = s_side ? s_side : main_s;

    if (s_side) {
        cudaEventRecord(s_evFork, main_s);
        cudaStreamWaitEvent(side_s, s_evFork, 0);
    }

    // ---- side stream: Wl, layer-1 scores, CSR (all overlap GEMM1) -----------
    k_wl<<<(300 * 8 + 255) / 256, t256, 0, side_s>>>(W1, al1, ar1, wl1, 300, 100);
    k_wl<<<(400 * 8 + 255) / 256, t256, 0, side_s>>>(W2, al2, ar2, wl2, 400, 128);
    k_scores_wl<<<nScoreBlocks, 128, 0, side_s>>>(init_emb, wl1, el, er, 300);
    if (s_side) cudaEventRecord(s_evS1, side_s);

    k_zero_int<<<(NN + 255) / 256, t256, 0, side_s>>>(cnt, NN);
    k_hist<<<(NE + 255) / 256, t256, 0, side_s>>>(dst, cnt);
    k_scan1<<<nScanBlocks, 1024, 0, side_s>>>(cnt, rowptr, bsum);
    k_scan2<<<1, 32, 0, side_s>>>(bsum, nScanBlocks);
    k_scan3<<<nScanBlocks, 1024, 0, side_s>>>(rowptr, bsum, cnt);
    k_scatter<<<(NE + 255) / 256, t256, 0, side_s>>>(src, dst, rowptr, cnt, ssrc);
    if (s_side) cudaEventRecord(s_evJoin, side_s);

    // ===================== layer 1 (Fin=300, Fout=400, Dh=100) ===============
    {
        dim3 grid((400 + BN - 1) / BN, (NN + BM - 1) / BM);
        k_gemm_tf32<<<grid, 256, 0, main_s>>>(init_emb, W1, proj1, NN, 400, 300);
    }
    if (s_side) {
        cudaStreamWaitEvent(main_s, s_evS1, 0);
        cudaStreamWaitEvent(main_s, s_evJoin, 0);
    }
    k_node<100><<<NN, 128, 0, main_s>>>(proj1, el, er, rowptr, ssrc, b1, x1, 1);
    if (s_side) cudaEventRecord(s_evX1, main_s);

    // ---- side: layer-2 scores from x1 (overlaps GEMM2; both only read x1) ---
    if (s_side) cudaStreamWaitEvent(side_s, s_evX1, 0);
    k_scores_wl<<<nScoreBlocks, 128, 0, side_s>>>(x1, wl2, el, er, 400);
    if (s_side) cudaEventRecord(s_evS2, side_s);

    // ===================== layer 2 (Fin=400, Fout=512, Dh=128) ===============
    {
        dim3 grid((512 + BN - 1) / BN, (NN + BM - 1) / BM);
        k_gemm_tf32<<<grid, 256, 0, main_s>>>(x1, W2, proj2, NN, 512, 400);
    }
    if (s_side) cudaStreamWaitEvent(main_s, s_evS2, 0);
    k_node<128><<<NN, 128, 0, main_s>>>(proj2, el, er, rowptr, ssrc, b2, out, 0);
}

// round 16
// speedup vs baseline: 1.5015x; 1.5015x over previous
#include <cuda_runtime.h>
#include <cuda_fp16.h>
#include <math.h>

#define NN 50000
#define NE 800000
#define NH 4
#define NEG 0.2f

// ---------------- scratch (static device globals; no allocs allowed) ----------
__device__ __half g_proj1[NN * 400];
__device__ float  g_x1[NN * 400];
__device__ __half g_proj2[NN * 512];
__device__ float  g_el[NN * NH];
__device__ float  g_er[NN * NH];
__device__ int    g_rowptr[NN + 1];
__device__ int    g_cnt[NN];
__device__ int    g_bsum[64];
__device__ int    g_ssrc[NE];

// ---------------- helpers ----------------------------------------------------
__device__ __forceinline__ float lrelu(float v) { return v > 0.f ? v : NEG * v; }

__device__ __forceinline__ unsigned f2tf32(float f) {
    unsigned r;
    asm("cvt.rna.tf32.f32 %0, %1;" : "=r"(r) : "f"(f));
    return r;
}

__device__ __forceinline__ void mma_tf32(float c[4], const unsigned a[4], const unsigned b[2]) {
    asm volatile(
        "mma.sync.aligned.m16n8k8.row.col.f32.tf32.tf32.f32 "
        "{%0,%1,%2,%3}, {%4,%5,%6,%7}, {%8,%9}, {%0,%1,%2,%3};"
        : "+f"(c[0]), "+f"(c[1]), "+f"(c[2]), "+f"(c[3])
        : "r"(a[0]), "r"(a[1]), "r"(a[2]), "r"(a[3]), "r"(b[0]), "r"(b[1]));
}

// ---------------- CSR build ---------------------------------------------------
__global__ void k_zero_int(int* p, int n) {
    int i = blockIdx.x * blockDim.x + threadIdx.x;
    if (i < n) p[i] = 0;
}

__global__ void k_hist(const int* __restrict__ dst, int* __restrict__ cnt) {
    int i = blockIdx.x * blockDim.x + threadIdx.x;
    if (i < NE) atomicAdd(&cnt[dst[i]], 1);
}

__global__ void k_scan1(const int* __restrict__ cnt, int* __restrict__ rowptr,
                        int* __restrict__ bsum) {
    __shared__ int sd[1024];
    int i = blockIdx.x * 1024 + threadIdx.x;
    int v = (i < NN) ? cnt[i] : 0;
    sd[threadIdx.x] = v;
    __syncthreads();
#pragma unroll
    for (int o = 1; o < 1024; o <<= 1) {
        int t = (threadIdx.x >= o) ? sd[threadIdx.x - o] : 0;
        __syncthreads();
        sd[threadIdx.x] += t;
        __syncthreads();
    }
    if (i < NN) rowptr[i + 1] = sd[threadIdx.x];
    if (threadIdx.x == 1023) bsum[blockIdx.x] = sd[1023];
}

__global__ void k_scan2(int* bsum, int nb) {
    if (threadIdx.x == 0) {
        int acc = 0;
        for (int b = 0; b < nb; b++) { int t = bsum[b]; bsum[b] = acc; acc += t; }
    }
}

__global__ void k_scan3(int* __restrict__ rowptr, const int* __restrict__ bsum,
                        int* __restrict__ cnt) {
    int i = blockIdx.x * blockDim.x + threadIdx.x;
    if (i < NN) {
        rowptr[i + 1] += bsum[i >> 10];
        cnt[i] = 0;
        if (i == 0) rowptr[0] = 0;
    }
}

__global__ void k_scatter(const int* __restrict__ src, const int* __restrict__ dst,
                          const int* __restrict__ rowptr, int* __restrict__ cnt,
                          int* __restrict__ ssrc) {
    int i = blockIdx.x * blockDim.x + threadIdx.x;
    if (i >= NE) return;
    int d = dst[i];
    int pos = rowptr[d] + atomicAdd(&cnt[d], 1);
    ssrc[pos] = src[i];
}

// ---------------- TF32 GEMM, register-staged double buffering (R10 proven) ---
#define BM 128
#define BN 128
#define BK 16
#define A_STRIDE (BK + 4)
#define B_STRIDE (BN + 8)

__device__ __forceinline__ void load_tileA(const float* __restrict__ A, int M, int K,
                                           int bm0, int k0, int tid, float4 pa[2]) {
#pragma unroll
    for (int u = 0; u < 2; u++) {
        int idx = tid + u * 256;
        int row = idx >> 2;
        int col = (idx & 3) * 4;
        int gm = bm0 + row, gk = k0 + col;
        float4 v = make_float4(0.f, 0.f, 0.f, 0.f);
        if (gm < M) {
            if (gk + 3 < K) v = *(const float4*)(A + (size_t)gm * K + gk);
            else {
                const float* ap = A + (size_t)gm * K;
                if (gk + 0 < K) v.x = ap[gk + 0];
                if (gk + 1 < K) v.y = ap[gk + 1];
                if (gk + 2 < K) v.z = ap[gk + 2];
            }
        }
        pa[u] = v;
    }
}

__device__ __forceinline__ void load_tileB(const float* __restrict__ B, int N, int K,
                                           int bn0, int k0, int tid, float4 pb[2]) {
#pragma unroll
    for (int u = 0; u < 2; u++) {
        int idx = tid + u * 256;
        int row = idx >> 5;
        int col = (idx & 31) * 4;
        int gk = k0 + row, gn = bn0 + col;
        float4 v = make_float4(0.f, 0.f, 0.f, 0.f);
        if (gk < K) {
            if (gn + 3 < N) v = *(const float4*)(B + (size_t)gk * N + gn);
            else {
                const float* bp = B + (size_t)gk * N;
                if (gn + 0 < N) v.x = bp[gn + 0];
                if (gn + 1 < N) v.y = bp[gn + 1];
                if (gn + 2 < N) v.z = bp[gn + 2];
            }
        }
        pb[u] = v;
    }
}

__device__ __forceinline__ void store_tileA(unsigned (*As)[A_STRIDE], int tid,
                                            const float4 pa[2]) {
#pragma unroll
    for (int u = 0; u < 2; u++) {
        int idx = tid + u * 256;
        int row = idx >> 2;
        int col = (idx & 3) * 4;
        As[row][col + 0] = f2tf32(pa[u].x);
        As[row][col + 1] = f2tf32(pa[u].y);
        As[row][col + 2] = f2tf32(pa[u].z);
        As[row][col + 3] = f2tf32(pa[u].w);
    }
}

__device__ __forceinline__ void store_tileB(unsigned (*Bs)[B_STRIDE], int tid,
                                            const float4 pb[2]) {
#pragma unroll
    for (int u = 0; u < 2; u++) {
        int idx = tid + u * 256;
        int row = idx >> 5;
        int col = (idx & 31) * 4;
        Bs[row][col + 0] = f2tf32(pb[u].x);
        Bs[row][col + 1] = f2tf32(pb[u].y);
        Bs[row][col + 2] = f2tf32(pb[u].z);
        Bs[row][col + 3] = f2tf32(pb[u].w);
    }
}

__global__ void __launch_bounds__(256, 2)
k_gemm_tf32(const float* __restrict__ A, const float* __restrict__ B,
            __half* __restrict__ C, int M, int N, int K) {
    __shared__ unsigned As[2][BM][A_STRIDE];
    __shared__ unsigned Bs[2][BK][B_STRIDE];

    const int tid  = threadIdx.x;
    const int lane = tid & 31;
    const int warp = tid >> 5;
    const int g    = lane >> 2;
    const int t4   = lane & 3;
    const int wm   = warp & 1;
    const int wn   = warp >> 1;
    const int bm0  = blockIdx.y * BM;
    const int bn0  = blockIdx.x * BN;

    float c[4][4][4];
#pragma unroll
    for (int mi = 0; mi < 4; mi++)
#pragma unroll
        for (int ni = 0; ni < 4; ni++)
#pragma unroll
            for (int q = 0; q < 4; q++) c[mi][ni][q] = 0.f;

    const int nk = (K + BK - 1) / BK;
    float4 pa[2], pb[2];

    load_tileA(A, M, K, bm0, 0, tid, pa);
    load_tileB(B, N, K, bn0, 0, tid, pb);
    store_tileA(As[0], tid, pa);
    store_tileB(Bs[0], tid, pb);
    __syncthreads();

    int buf = 0;
    for (int kt = 0; kt < nk; kt++) {
        if (kt + 1 < nk) {
            load_tileA(A, M, K, bm0, (kt + 1) * BK, tid, pa);
            load_tileB(B, N, K, bn0, (kt + 1) * BK, tid, pb);
        }

#pragma unroll
        for (int kk = 0; kk < BK; kk += 8) {
            unsigned af[4][4], bf[4][2];
#pragma unroll
            for (int mi = 0; mi < 4; mi++) {
                int r0 = wm * 64 + mi * 16;
                af[mi][0] = As[buf][r0 + g    ][kk + t4    ];
                af[mi][1] = As[buf][r0 + g + 8][kk + t4    ];
                af[mi][2] = As[buf][r0 + g    ][kk + t4 + 4];
                af[mi][3] = As[buf][r0 + g + 8][kk + t4 + 4];
            }
#pragma unroll
            for (int ni = 0; ni < 4; ni++) {
                int c0 = wn * 32 + ni * 8;
                bf[ni][0] = Bs[buf][kk + t4    ][c0 + g];
                bf[ni][1] = Bs[buf][kk + t4 + 4][c0 + g];
            }
#pragma unroll
            for (int mi = 0; mi < 4; mi++)
#pragma unroll
                for (int ni = 0; ni < 4; ni++)
                    mma_tf32(c[mi][ni], af[mi], bf[ni]);
        }

        if (kt + 1 < nk) {
            store_tileA(As[buf ^ 1], tid, pa);
            store_tileB(Bs[buf ^ 1], tid, pb);
        }
        __syncthreads();
        buf ^= 1;
    }

    // epilogue: fp16 half2 stores (col0 always even; N even)
#pragma unroll
    for (int mi = 0; mi < 4; mi++) {
        int row0 = bm0 + wm * 64 + mi * 16;
#pragma unroll
        for (int ni = 0; ni < 4; ni++) {
            int col0 = bn0 + wn * 32 + ni * 8 + 2 * t4;
            if (col0 >= N) continue;
            int r = row0 + g;
            if (r < M)
                *(__half2*)(C + (size_t)r * N + col0) =
                    __floats2half2_rn(c[mi][ni][0], c[mi][ni][1]);
            r = row0 + g + 8;
            if (r < M)
                *(__half2*)(C + (size_t)r * N + col0) =
                    __floats2half2_rn(c[mi][ni][2], c[mi][ni][3]);
        }
    }
}

// ---------------- per-node attention scores el/er (fp16 proj) ----------------
__global__ void k_scores(const __half* __restrict__ proj,
                         const float* __restrict__ al, const float* __restrict__ ar,
                         float* __restrict__ el, float* __restrict__ er, int Dh) {
    int n = blockIdx.x;
    int w = threadIdx.x >> 5, lane = threadIdx.x & 31;
    const __half* p = proj + (size_t)n * NH * Dh + w * Dh;
    float sl = 0.f, sr = 0.f;
    for (int d = lane; d < Dh; d += 32) {
        float v = __half2float(p[d]);
        sl += v * al[w * Dh + d];
        sr += v * ar[w * Dh + d];
    }
#pragma unroll
    for (int o = 16; o > 0; o >>= 1) {
        sl += __shfl_down_sync(0xffffffffu, sl, o);
        sr += __shfl_down_sync(0xffffffffu, sr, o);
    }
    if (lane == 0) { el[n * NH + w] = sl; er[n * NH + w] = sr; }
}

// ---------------- fused per-dst-node softmax + aggregate + bias + act --------
template <int DH>
__global__ void __launch_bounds__(128)
k_node(const __half* __restrict__ proj, const float* __restrict__ el,
       const float* __restrict__ er, const int* __restrict__ rowptr,
       const int* __restrict__ ssrc, const float* __restrict__ bias,
       float* __restrict__ out, int act) {
    const int F = NH * DH;
    int n = blockIdx.x;
    int tid = threadIdx.x, w = tid >> 5, lane = tid & 31;
    int beg = rowptr[n], deg = rowptr[n + 1] - beg;
    float* o = out + (size_t)n * F;

    if (deg == 0) {
        for (int f = tid; f < F; f += 128) {
            float v = bias[f];
            o[f] = act ? lrelu(v) : v;
        }
        return;
    }

    __shared__ float s_er[NH], s_m[NH], s_is[NH];
    __shared__ float s_alpha[32 * NH];
    __shared__ int   s_src[32];
    if (tid < NH) s_er[tid] = er[n * NH + tid];
    __syncthreads();

    float erw = s_er[w];
    float mx = -INFINITY;
    for (int e = lane; e < deg; e += 32) {
        int s = ssrc[beg + e];
        mx = fmaxf(mx, lrelu(el[s * NH + w] + erw));
    }
#pragma unroll
    for (int off = 16; off; off >>= 1) mx = fmaxf(mx, __shfl_xor_sync(0xffffffffu, mx, off));
    float sum = 0.f;
    for (int e = lane; e < deg; e += 32) {
        int s = ssrc[beg + e];
        sum += expf(lrelu(el[s * NH + w] + erw) - mx);
    }
#pragma unroll
    for (int off = 16; off; off >>= 1) sum += __shfl_xor_sync(0xffffffffu, sum, off);
    if (lane == 0) { s_m[w] = mx; s_is[w] = 1.f / (sum + 1e-9f); }

    const int f = tid * 4;
    const int h = f / DH;
    float4 acc = make_float4(0.f, 0.f, 0.f, 0.f);

    for (int c0 = 0; c0 < deg; c0 += 32) {
        int cn = min(32, deg - c0);
        __syncthreads();
        for (int i = tid; i < cn * NH; i += 128) {
            int e = i >> 2, hh = i & 3;
            int s = ssrc[beg + c0 + e];
            if (hh == 0) s_src[e] = s;
            s_alpha[i] = expf(lrelu(el[s * NH + hh] + s_er[hh]) - s_m[hh]) * s_is[hh];
        }
        __syncthreads();
        if (f < F) {
            if (cn == 32) {
#pragma unroll 4
                for (int e = 0; e < 32; e++) {
                    float a = s_alpha[e * NH + h];
                    uint2 raw = *(const uint2*)(proj + (size_t)s_src[e] * F + f);
                    float2 v01 = __half22float2(*(__half2*)&raw.x);
                    float2 v23 = __half22float2(*(__half2*)&raw.y);
                    acc.x += v01.x * a;
                    acc.y += v01.y * a;
                    acc.z += v23.x * a;
                    acc.w += v23.y * a;
                }
            } else {
                for (int e = 0; e < cn; e++) {
                    float a = s_alpha[e * NH + h];
                    uint2 raw = *(const uint2*)(proj + (size_t)s_src[e] * F + f);
                    float2 v01 = __half22float2(*(__half2*)&raw.x);
                    float2 v23 = __half22float2(*(__half2*)&raw.y);
                    acc.x += v01.x * a;
                    acc.y += v01.y * a;
                    acc.z += v23.x * a;
                    acc.w += v23.y * a;
                }
            }
        }
    }

    if (f < F) {
        float4 b4 = *(const float4*)(bias + f);
        float4 r;
        r.x = acc.x + b4.x; r.y = acc.y + b4.y;
        r.z = acc.z + b4.z; r.w = acc.w + b4.w;
        if (act) { r.x = lrelu(r.x); r.y = lrelu(r.y); r.z = lrelu(r.z); r.w = lrelu(r.w); }
        *(float4*)(o + f) = r;
    }
}

// ---------------- launch (exact R10 topology) --------------------------------
extern "C" void kernel_launch(void* const* d_in, const int* in_sizes, int n_in,
                              void* d_out, int out_size) {
    const float* init_emb = (const float*)d_in[0];
    const float* W1  = (const float*)d_in[1];
    const float* al1 = (const float*)d_in[2];
    const float* ar1 = (const float*)d_in[3];
    const float* b1  = (const float*)d_in[4];
    const float* W2  = (const float*)d_in[5];
    const float* al2 = (const float*)d_in[6];
    const float* ar2 = (const float*)d_in[7];
    const float* b2  = (const float*)d_in[8];
    const int*   src = (const int*)d_in[9];
    const int*   dst = (const int*)d_in[10];
    float* out = (float*)d_out;

    __half *proj1, *proj2;
    float *x1, *el, *er;
    int *rowptr, *cnt, *bsum, *ssrc;
    cudaGetSymbolAddress((void**)&proj1,  g_proj1);
    cudaGetSymbolAddress((void**)&x1,     g_x1);
    cudaGetSymbolAddress((void**)&proj2,  g_proj2);
    cudaGetSymbolAddress((void**)&el,     g_el);
    cudaGetSymbolAddress((void**)&er,     g_er);
    cudaGetSymbolAddress((void**)&rowptr, g_rowptr);
    cudaGetSymbolAddress((void**)&cnt,    g_cnt);
    cudaGetSymbolAddress((void**)&bsum,   g_bsum);
    cudaGetSymbolAddress((void**)&ssrc,   g_ssrc);

    dim3 t256(256);
    const int nScanBlocks = (NN + 1023) / 1024;

    static cudaStream_t s_side = nullptr;
    static cudaEvent_t  s_evFork = nullptr, s_evJoin = nullptr;
    if (!s_side) {
        if (cudaStreamCreateWithFlags(&s_side, cudaStreamNonBlocking) != cudaSuccess)
            s_side = nullptr;
        if (s_side) {
            cudaEventCreateWithFlags(&s_evFork, cudaEventDisableTiming);
            cudaEventCreateWithFlags(&s_evJoin, cudaEventDisableTiming);
        }
    }

    cudaStream_t main_s = 0;
    cudaStream_t csr_s  = s_side ? s_side : main_s;

    if (s_side) {
        cudaEventRecord(s_evFork, main_s);
        cudaStreamWaitEvent(csr_s, s_evFork, 0);
    }

    // ---------------- CSR build (side stream, overlaps GEMM1) ----------------
    k_zero_int<<<(NN + 255) / 256, t256, 0, csr_s>>>(cnt, NN);
    k_hist<<<(NE + 255) / 256, t256, 0, csr_s>>>(dst, cnt);
    k_scan1<<<nScanBlocks, 1024, 0, csr_s>>>(cnt, rowptr, bsum);
    k_scan2<<<1, 32, 0, csr_s>>>(bsum, nScanBlocks);
    k_scan3<<<nScanBlocks, 1024, 0, csr_s>>>(rowptr, bsum, cnt);
    k_scatter<<<(NE + 255) / 256, t256, 0, csr_s>>>(src, dst, rowptr, cnt, ssrc);

    if (s_side) cudaEventRecord(s_evJoin, csr_s);

    // ===================== layer 1 (Fin=300, Fout=400, Dh=100) ===============
    {
        dim3 grid((400 + BN - 1) / BN, (NN + BM - 1) / BM);
        k_gemm_tf32<<<grid, 256, 0, main_s>>>(init_emb, W1, proj1, NN, 400, 300);
    }
    k_scores<<<NN, 128, 0, main_s>>>(proj1, al1, ar1, el, er, 100);

    if (s_side) cudaStreamWaitEvent(main_s, s_evJoin, 0);   // join before k_node

    k_node<100><<<NN, 128, 0, main_s>>>(proj1, el, er, rowptr, ssrc, b1, x1, 1);

    // ===================== layer 2 (Fin=400, Fout=512, Dh=128) ===============
    {
        dim3 grid((512 + BN - 1) / BN, (NN + BM - 1) / BM);
        k_gemm_tf32<<<grid, 256, 0, main_s>>>(x1, W2, proj2, NN, 512, 400);
    }
    k_scores<<<NN, 128, 0, main_s>>>(proj2, al2, ar2, el, er, 128);
    k_node<128><<<NN, 128, 0, main_s>>>(proj2, el, er, rowptr, ssrc, b2, out, 0);
}